// round 1
// baseline (speedup 1.0000x reference)
#include <cuda_runtime.h>
#include <cuda_bf16.h>
#include <math.h>

// Problem constants (match reference)
#define NN 100000
#define EE 1600000
#define F_IN 256
#define F_OUT 64

// Scratch (device globals; no runtime allocation allowed)
__device__ float g_x[(size_t)NN * F_OUT];   // projected features
__device__ float g_q[NN];
__device__ float g_k[NN];
__device__ int   g_rp[NN + 1];

// ---------------------------------------------------------------------------
// Kernel 1: x = nf @ Wv   (M=100000, K=256, N=64) fp32 SGEMM
// BM=64 rows per block, BK=16, full 64 output cols. 128 threads.
// Each thread: 8 rows x 4 cols micro-tile.
// ---------------------------------------------------------------------------
#define BM 64
#define BK 16

__global__ __launch_bounds__(128) void gemm_kernel(
    const float* __restrict__ nf, const float* __restrict__ Wv,
    float* __restrict__ xout, int n)
{
    __shared__ float As[BK][BM];      // [k][m]
    __shared__ float Bs[BK * F_OUT];  // [k][f] contiguous

    const int t  = threadIdx.x;
    const int rx = t >> 4;    // 0..7  -> rows rx*8 .. rx*8+7
    const int cx = t & 15;    // 0..15 -> cols cx*4 .. cx*4+3
    const int m0 = blockIdx.x * BM;

    const int am  = t >> 2;   // 0..31
    const int akg = t & 3;    // 0..3  (group of 4 k's)

    float acc[8][4];
#pragma unroll
    for (int j = 0; j < 8; ++j)
#pragma unroll
        for (int c = 0; c < 4; ++c) acc[j][c] = 0.0f;

    for (int k0 = 0; k0 < F_IN; k0 += BK) {
        // A tile: 64 rows x 16 k's -> transposed into As[k][m]
#pragma unroll
        for (int half = 0; half < 2; ++half) {
            int m  = am + half * 32;
            int gm = m0 + m;
            float4 v = make_float4(0.f, 0.f, 0.f, 0.f);
            if (gm < n)
                v = *reinterpret_cast<const float4*>(
                        &nf[(size_t)gm * F_IN + k0 + akg * 4]);
            As[akg * 4 + 0][m] = v.x;
            As[akg * 4 + 1][m] = v.y;
            As[akg * 4 + 2][m] = v.z;
            As[akg * 4 + 3][m] = v.w;
        }
        // B tile: contiguous 16x64 floats = Wv + k0*64
#pragma unroll
        for (int half = 0; half < 2; ++half) {
            int idx = t + half * 128;  // float4 index 0..255
            reinterpret_cast<float4*>(Bs)[idx] =
                reinterpret_cast<const float4*>(&Wv[k0 * F_OUT])[idx];
        }
        __syncthreads();

#pragma unroll
        for (int k = 0; k < BK; ++k) {
            float4 b4 = *reinterpret_cast<const float4*>(&Bs[k * F_OUT + cx * 4]);
            float4 a0 = *reinterpret_cast<const float4*>(&As[k][rx * 8]);
            float4 a1 = *reinterpret_cast<const float4*>(&As[k][rx * 8 + 4]);
            float a[8] = {a0.x, a0.y, a0.z, a0.w, a1.x, a1.y, a1.z, a1.w};
#pragma unroll
            for (int j = 0; j < 8; ++j) {
                acc[j][0] = fmaf(a[j], b4.x, acc[j][0]);
                acc[j][1] = fmaf(a[j], b4.y, acc[j][1]);
                acc[j][2] = fmaf(a[j], b4.z, acc[j][2]);
                acc[j][3] = fmaf(a[j], b4.w, acc[j][3]);
            }
        }
        __syncthreads();
    }

#pragma unroll
    for (int j = 0; j < 8; ++j) {
        int gm = m0 + rx * 8 + j;
        if (gm < n) {
            float4 v = make_float4(acc[j][0], acc[j][1], acc[j][2], acc[j][3]);
            *reinterpret_cast<float4*>(&xout[(size_t)gm * F_OUT + cx * 4]) = v;
        }
    }
}

// ---------------------------------------------------------------------------
// Kernel 2: q[i] = x[i]·wq, k[i] = x[i]·wk   (warp per node)
// ---------------------------------------------------------------------------
__global__ void qk_kernel(const float* __restrict__ x,
                          const float* __restrict__ wq,
                          const float* __restrict__ wk,
                          float* __restrict__ q, float* __restrict__ kk, int n)
{
    int warp = (blockIdx.x * blockDim.x + threadIdx.x) >> 5;
    int lane = threadIdx.x & 31;
    if (warp >= n) return;
    float x0 = x[(size_t)warp * F_OUT + lane];
    float x1 = x[(size_t)warp * F_OUT + 32 + lane];
    float qp = x0 * wq[lane] + x1 * wq[lane + 32];
    float kp = x0 * wk[lane] + x1 * wk[lane + 32];
#pragma unroll
    for (int o = 16; o; o >>= 1) {
        qp += __shfl_xor_sync(0xFFFFFFFFu, qp, o);
        kp += __shfl_xor_sync(0xFFFFFFFFu, kp, o);
    }
    if (lane == 0) { q[warp] = qp; kk[warp] = kp; }
}

// ---------------------------------------------------------------------------
// Kernel 3: row_ptr by binary search (row is sorted)
// ---------------------------------------------------------------------------
__global__ void rowptr_kernel(const int* __restrict__ row, int* __restrict__ rp,
                              int n, int e)
{
    int i = blockIdx.x * blockDim.x + threadIdx.x;
    if (i > n) return;
    int lo = 0, hi = e;
    while (lo < hi) {
        int mid = (lo + hi) >> 1;
        if (row[mid] < i) lo = mid + 1; else hi = mid;
    }
    rp[i] = lo;
}

// ---------------------------------------------------------------------------
// Kernel 4: segment softmax + attention-weighted aggregation (warp per node)
// ---------------------------------------------------------------------------
__global__ void gat_kernel(const int* __restrict__ rp, const int* __restrict__ col,
                           const float* __restrict__ x, const float* __restrict__ q,
                           const float* __restrict__ kk, const float* __restrict__ b,
                           float* __restrict__ out, int n)
{
    int i    = (blockIdx.x * blockDim.x + threadIdx.x) >> 5;
    int lane = threadIdx.x & 31;
    if (i >= n) return;

    int s = rp[i], e = rp[i + 1];
    float bias0 = b[lane], bias1 = b[lane + 32];
    float* orow = &out[(size_t)i * F_OUT];
    if (e == s) {  // empty segment: out = b
        orow[lane] = bias0;
        orow[lane + 32] = bias1;
        return;
    }
    float qi = q[i];

    // pass 1: segment max
    float m = -INFINITY;
    for (int t = s + lane; t < e; t += 32) {
        float l = kk[col[t]] + qi;
        l = (l > 0.f) ? l : 0.2f * l;
        m = fmaxf(m, l);
    }
#pragma unroll
    for (int o = 16; o; o >>= 1) m = fmaxf(m, __shfl_xor_sync(0xFFFFFFFFu, m, o));

    // pass 2: denom
    float ssum = 0.f;
    for (int t = s + lane; t < e; t += 32) {
        float l = kk[col[t]] + qi;
        l = (l > 0.f) ? l : 0.2f * l;
        ssum += __expf(l - m);
    }
#pragma unroll
    for (int o = 16; o; o >>= 1) ssum += __shfl_xor_sync(0xFFFFFFFFu, ssum, o);
    float inv = 1.0f / ssum;

    // pass 3: all 32 lanes cooperate per edge (2 features per lane)
    float a0 = 0.f, a1 = 0.f;
    for (int t = s; t < e; ++t) {
        int c = col[t];
        float l = kk[c] + qi;
        l = (l > 0.f) ? l : 0.2f * l;
        float w = __expf(l - m) * inv;
        const float* xr = &x[(size_t)c * F_OUT];
        a0 = fmaf(w, xr[lane], a0);
        a1 = fmaf(w, xr[lane + 32], a1);
    }
    orow[lane] = a0 + bias0;
    orow[lane + 32] = a1 + bias1;
}

// ---------------------------------------------------------------------------
extern "C" void kernel_launch(void* const* d_in, const int* in_sizes, int n_in,
                              void* d_out, int out_size)
{
    const float* nf  = (const float*)d_in[0];   // [N, 256]
    const int*   row = (const int*)d_in[1];     // [E]
    const int*   col = (const int*)d_in[2];     // [E]
    const float* Wv  = (const float*)d_in[3];   // [256, 64]
    const float* wq  = (const float*)d_in[4];   // [64]
    const float* wk  = (const float*)d_in[5];   // [64]
    const float* b   = (const float*)d_in[6];   // [64]
    float* out = (float*)d_out;                  // [N, 64]

    const int n = NN;
    const int e = EE;

    float *xbuf, *qbuf, *kbuf;
    int *rpbuf;
    cudaGetSymbolAddress((void**)&xbuf, g_x);
    cudaGetSymbolAddress((void**)&qbuf, g_q);
    cudaGetSymbolAddress((void**)&kbuf, g_k);
    cudaGetSymbolAddress((void**)&rpbuf, g_rp);

    // 1) projection GEMM
    gemm_kernel<<<(n + BM - 1) / BM, 128>>>(nf, Wv, xbuf, n);
    // 2) per-node scalar q/k (warp per node; 8 warps / block)
    qk_kernel<<<(n + 7) / 8, 256>>>(xbuf, wq, wk, qbuf, kbuf, n);
    // 3) CSR offsets
    rowptr_kernel<<<(n + 1 + 255) / 256, 256>>>(row, rpbuf, n, e);
    // 4) softmax + aggregation (warp per node)
    gat_kernel<<<(n + 7) / 8, 256>>>(rpbuf, col, xbuf, qbuf, kbuf, b, out, n);
}

// round 3
// speedup vs baseline: 1.2083x; 1.2083x over previous
#include <cuda_runtime.h>
#include <cuda_bf16.h>
#include <math.h>

// Problem constants (match reference)
#define NN 100000
#define EE 1600000
#define F_IN 256
#define F_OUT 64

// Scratch (device globals; no runtime allocation allowed)
__device__ float g_x[(size_t)NN * F_OUT];   // projected features
__device__ float g_q[NN];
__device__ float g_k[NN];
__device__ int   g_rp[NN + 1];

// ---------------------------------------------------------------------------
// Kernel 1: x = nf @ Wv   (M=100000, K=256, N=64) fp32 SGEMM
// BM=64 rows per block, BK=16, full 64 output cols. 128 threads.
// Each thread: 8 rows x 4 cols micro-tile.
// Fused epilogue: q[i] = x[i]·wq, k[i] = x[i]·wk via 16-lane shfl reduction.
// ---------------------------------------------------------------------------
#define BM 64
#define BK 16

__global__ __launch_bounds__(128) void gemm_kernel(
    const float* __restrict__ nf, const float* __restrict__ Wv,
    const float* __restrict__ wq, const float* __restrict__ wk,
    float* __restrict__ xout, float* __restrict__ qo, float* __restrict__ ko,
    int n)
{
    __shared__ float As[BK][BM];      // [k][m]
    __shared__ float Bs[BK * F_OUT];  // [k][f] contiguous

    const int t  = threadIdx.x;
    const int rx = t >> 4;    // 0..7  -> rows rx*8 .. rx*8+7
    const int cx = t & 15;    // 0..15 -> cols cx*4 .. cx*4+3
    const int m0 = blockIdx.x * BM;

    const int am  = t >> 2;   // 0..31
    const int akg = t & 3;    // 0..3  (group of 4 k's)

    float acc[8][4];
#pragma unroll
    for (int j = 0; j < 8; ++j)
#pragma unroll
        for (int c = 0; c < 4; ++c) acc[j][c] = 0.0f;

    for (int k0 = 0; k0 < F_IN; k0 += BK) {
        // A tile: 64 rows x 16 k's -> transposed into As[k][m]
#pragma unroll
        for (int half = 0; half < 2; ++half) {
            int m  = am + half * 32;
            int gm = m0 + m;
            float4 v = make_float4(0.f, 0.f, 0.f, 0.f);
            if (gm < n)
                v = *reinterpret_cast<const float4*>(
                        &nf[(size_t)gm * F_IN + k0 + akg * 4]);
            As[akg * 4 + 0][m] = v.x;
            As[akg * 4 + 1][m] = v.y;
            As[akg * 4 + 2][m] = v.z;
            As[akg * 4 + 3][m] = v.w;
        }
        // B tile: contiguous 16x64 floats = Wv + k0*64
#pragma unroll
        for (int half = 0; half < 2; ++half) {
            int idx = t + half * 128;  // float4 index 0..255
            reinterpret_cast<float4*>(Bs)[idx] =
                reinterpret_cast<const float4*>(&Wv[k0 * F_OUT])[idx];
        }
        __syncthreads();

#pragma unroll
        for (int k = 0; k < BK; ++k) {
            float4 b4 = *reinterpret_cast<const float4*>(&Bs[k * F_OUT + cx * 4]);
            float4 a0 = *reinterpret_cast<const float4*>(&As[k][rx * 8]);
            float4 a1 = *reinterpret_cast<const float4*>(&As[k][rx * 8 + 4]);
            float a[8] = {a0.x, a0.y, a0.z, a0.w, a1.x, a1.y, a1.z, a1.w};
#pragma unroll
            for (int j = 0; j < 8; ++j) {
                acc[j][0] = fmaf(a[j], b4.x, acc[j][0]);
                acc[j][1] = fmaf(a[j], b4.y, acc[j][1]);
                acc[j][2] = fmaf(a[j], b4.z, acc[j][2]);
                acc[j][3] = fmaf(a[j], b4.w, acc[j][3]);
            }
        }
        __syncthreads();
    }

    // write x tile
#pragma unroll
    for (int j = 0; j < 8; ++j) {
        int gm = m0 + rx * 8 + j;
        if (gm < n) {
            float4 v = make_float4(acc[j][0], acc[j][1], acc[j][2], acc[j][3]);
            *reinterpret_cast<float4*>(&xout[(size_t)gm * F_OUT + cx * 4]) = v;
        }
    }

    // fused q/k epilogue: reduce across the 16 cx-lanes of each row group.
    // lane-in-warp = (rx&1)*16 + cx, so xor offsets 1..8 stay inside the group.
    float wqv0 = wq[cx * 4 + 0], wqv1 = wq[cx * 4 + 1],
          wqv2 = wq[cx * 4 + 2], wqv3 = wq[cx * 4 + 3];
    float wkv0 = wk[cx * 4 + 0], wkv1 = wk[cx * 4 + 1],
          wkv2 = wk[cx * 4 + 2], wkv3 = wk[cx * 4 + 3];
#pragma unroll
    for (int j = 0; j < 8; ++j) {
        float qp = acc[j][0] * wqv0 + acc[j][1] * wqv1
                 + acc[j][2] * wqv2 + acc[j][3] * wqv3;
        float kp = acc[j][0] * wkv0 + acc[j][1] * wkv1
                 + acc[j][2] * wkv2 + acc[j][3] * wkv3;
#pragma unroll
        for (int o = 1; o < 16; o <<= 1) {
            qp += __shfl_xor_sync(0xFFFFFFFFu, qp, o);
            kp += __shfl_xor_sync(0xFFFFFFFFu, kp, o);
        }
        int gm = m0 + rx * 8 + j;
        if (cx == 0 && gm < n) { qo[gm] = qp; ko[gm] = kp; }
    }
}

// ---------------------------------------------------------------------------
// Kernel 2: row_ptr by binary search (row is sorted)
// ---------------------------------------------------------------------------
__global__ void rowptr_kernel(const int* __restrict__ row, int* __restrict__ rp,
                              int n, int e)
{
    int i = blockIdx.x * blockDim.x + threadIdx.x;
    if (i > n) return;
    int lo = 0, hi = e;
    while (lo < hi) {
        int mid = (lo + hi) >> 1;
        if (row[mid] < i) lo = mid + 1; else hi = mid;
    }
    rp[i] = lo;
}

// ---------------------------------------------------------------------------
// Kernel 3: fused segment softmax + aggregation (warp per node, single pass)
//   out[i] = (sum_e exp(l_e) * x[col_e]) / (sum_e exp(l_e)) + b
// Softmax shift-invariance lets us skip the max pass (logits are O(10), no
// overflow; the shift cancels in the normalization).
// Per 32-edge chunk: each lane computes exp for one edge (coalesced col read,
// one kk gather), then the warp processes 2 edges/step with 16 lanes x float4
// each (full 256B coalesced LDG.128 per edge). The pair loop has a UNIFORM
// trip count across the warp: every lane executes every shfl (clamped slot),
// and only the gather/FMA is predicated. (R1's bug: divergent shfl counts for
// odd cnt -> UB -> wild index -> illegal access.)
// ---------------------------------------------------------------------------
__global__ __launch_bounds__(256) void gat_kernel(
    const int* __restrict__ rp, const int* __restrict__ col,
    const float* __restrict__ x, const float* __restrict__ q,
    const float* __restrict__ kk, const float* __restrict__ b,
    float* __restrict__ out, int n)
{
    int i    = (blockIdx.x * blockDim.x + threadIdx.x) >> 5;
    int lane = threadIdx.x & 31;
    if (i >= n) return;

    const int half = lane >> 4;   // 0 or 1: which edge of the pair
    const int fl   = lane & 15;   // feature float4 index 0..15

    float4 bias = reinterpret_cast<const float4*>(b)[fl];
    float4* orow4 = reinterpret_cast<float4*>(&out[(size_t)i * F_OUT]);

    int s = rp[i], e = rp[i + 1];
    if (e == s) {               // empty segment: out = b
        if (half == 0) orow4[fl] = bias;
        return;
    }
    float qi = q[i];

    float4 acc = make_float4(0.f, 0.f, 0.f, 0.f);
    float ssum = 0.f;

    for (int base = s; base < e; base += 32) {
        int t = base + lane;
        float ev = 0.f;
        int c = 0;
        if (t < e) {
            c = col[t];
            float l = kk[c] + qi;
            l = (l > 0.f) ? l : 0.2f * l;
            ev = __expf(l);
        }
        ssum += ev;

        int cnt = min(e - base, 32);
        for (int j0 = 0; j0 < cnt; j0 += 2) {
            int j    = j0 + half;          // this half's edge slot
            int jsafe = min(j, cnt - 1);   // uniform, valid shfl source
            float w = __shfl_sync(0xFFFFFFFFu, ev, jsafe);
            int  cc = __shfl_sync(0xFFFFFFFFu, c,  jsafe);
            if (j < cnt) {
                float4 xv = reinterpret_cast<const float4*>(
                                &x[(size_t)cc * F_OUT])[fl];
                acc.x = fmaf(w, xv.x, acc.x);
                acc.y = fmaf(w, xv.y, acc.y);
                acc.z = fmaf(w, xv.z, acc.z);
                acc.w = fmaf(w, xv.w, acc.w);
            }
        }
    }

    // reduce denom across warp
#pragma unroll
    for (int o = 16; o; o >>= 1) ssum += __shfl_xor_sync(0xFFFFFFFFu, ssum, o);
    float inv = 1.0f / ssum;

    // combine the two half-warp accumulators (same features, different edges)
    acc.x += __shfl_xor_sync(0xFFFFFFFFu, acc.x, 16);
    acc.y += __shfl_xor_sync(0xFFFFFFFFu, acc.y, 16);
    acc.z += __shfl_xor_sync(0xFFFFFFFFu, acc.z, 16);
    acc.w += __shfl_xor_sync(0xFFFFFFFFu, acc.w, 16);

    if (half == 0) {
        float4 r;
        r.x = fmaf(acc.x, inv, bias.x);
        r.y = fmaf(acc.y, inv, bias.y);
        r.z = fmaf(acc.z, inv, bias.z);
        r.w = fmaf(acc.w, inv, bias.w);
        orow4[fl] = r;
    }
}

// ---------------------------------------------------------------------------
extern "C" void kernel_launch(void* const* d_in, const int* in_sizes, int n_in,
                              void* d_out, int out_size)
{
    const float* nf  = (const float*)d_in[0];   // [N, 256]
    const int*   row = (const int*)d_in[1];     // [E]
    const int*   col = (const int*)d_in[2];     // [E]
    const float* Wv  = (const float*)d_in[3];   // [256, 64]
    const float* wq  = (const float*)d_in[4];   // [64]
    const float* wk  = (const float*)d_in[5];   // [64]
    const float* b   = (const float*)d_in[6];   // [64]
    float* out = (float*)d_out;                  // [N, 64]

    const int n = NN;
    const int e = EE;

    float *xbuf, *qbuf, *kbuf;
    int *rpbuf;
    cudaGetSymbolAddress((void**)&xbuf, g_x);
    cudaGetSymbolAddress((void**)&qbuf, g_q);
    cudaGetSymbolAddress((void**)&kbuf, g_k);
    cudaGetSymbolAddress((void**)&rpbuf, g_rp);

    // 1) projection GEMM + fused q/k epilogue
    gemm_kernel<<<(n + BM - 1) / BM, 128>>>(nf, Wv, wq, wk, xbuf, qbuf, kbuf, n);
    // 2) CSR offsets (independent of GEMM; cheap)
    rowptr_kernel<<<(n + 1 + 255) / 256, 256>>>(row, rpbuf, n, e);
    // 3) fused softmax + aggregation (warp per node)
    gat_kernel<<<(n + 7) / 8, 256>>>(rpbuf, col, xbuf, qbuf, kbuf, b, out, n);
}

// round 4
// speedup vs baseline: 1.6310x; 1.3499x over previous
#include <cuda_runtime.h>
#include <cuda_bf16.h>
#include <math.h>

// Problem constants (match reference)
#define NN 100000
#define EE 1600000
#define F_IN 256
#define F_OUT 64

// Scratch (device globals; no runtime allocation allowed)
__device__ float g_x[(size_t)NN * F_OUT];   // projected features
__device__ float g_q[NN];
__device__ float g_k[NN];
__device__ int   g_rp[NN + 1];

// ---------------------------------------------------------------------------
// tf32 helpers
// ---------------------------------------------------------------------------
__device__ __forceinline__ unsigned tf32u(float x) {
    unsigned u;
    asm("cvt.rna.tf32.f32 %0, %1;" : "=r"(u) : "f"(x));
    return u;
}
__device__ __forceinline__ float tf32f(float x) {
    return __uint_as_float(tf32u(x));
}
__device__ __forceinline__ void mma_tf32(float* d,
    unsigned a0, unsigned a1, unsigned a2, unsigned a3,
    unsigned b0, unsigned b1)
{
    asm("mma.sync.aligned.m16n8k8.row.col.f32.tf32.tf32.f32 "
        "{%0,%1,%2,%3},{%4,%5,%6,%7},{%8,%9},{%0,%1,%2,%3};"
        : "+f"(d[0]), "+f"(d[1]), "+f"(d[2]), "+f"(d[3])
        : "r"(a0), "r"(a1), "r"(a2), "r"(a3), "r"(b0), "r"(b1));
}

// ---------------------------------------------------------------------------
// Kernel 1: x = nf @ Wv  via tensor cores (tf32, 2-pass A-split for accuracy)
// BM=128, BN=64, BK=32. 128 threads = 4 warps; warp w owns rows [32w,32w+32)
// = 2 x m16 tiles, all 8 n8 tiles. Accuracy: A = A_hi + A_lo (tf32 each),
// D = A_hi*B + A_lo*B with B tf32-rounded once -> out rel err ~2e-4.
// Fused epilogue: q = x*wq, k = x*wk reduced over the 4 lanes per row.
// ---------------------------------------------------------------------------
#define A_STRIDE 36   // floats per A row in smem (conflict-free frag loads)
#define B_STRIDE 72   // floats per B row in smem

__global__ __launch_bounds__(128) void gemm_tc_kernel(
    const float* __restrict__ nf, const float* __restrict__ Wv,
    const float* __restrict__ wq, const float* __restrict__ wk,
    float* __restrict__ xout, float* __restrict__ qo, float* __restrict__ ko,
    int n)
{
    __shared__ __align__(16) float As[128 * A_STRIDE];  // fp32 A tile 128x32
    __shared__ __align__(16) float Bs[32 * B_STRIDE];   // tf32 B tile 32x64
    __shared__ float sWq[64], sWk[64];

    const int t    = threadIdx.x;
    const int lane = t & 31;
    const int w    = t >> 5;
    const int m0   = blockIdx.x * 128;

    if (t < 64) { sWq[t] = wq[t]; sWk[t] = wk[t]; }

    // load mappings
    const int aq = t & 7;          // A col-quad 0..7
    const int ar = t >> 3;         // A base row 0..15 (+16*i)
    const int bq = t & 15;         // B col-quad 0..15
    const int bk = t >> 4;         // B base k 0..7 (+8*i)

    float4 pa[8];
    float4 pb[4];

    // prefetch tile 0
#pragma unroll
    for (int i = 0; i < 8; ++i) {
        int gm = m0 + ar + 16 * i;
        pa[i] = (gm < n)
            ? *reinterpret_cast<const float4*>(&nf[(size_t)gm * F_IN + aq * 4])
            : make_float4(0.f, 0.f, 0.f, 0.f);
    }
#pragma unroll
    for (int i = 0; i < 4; ++i) {
        float4 v = *reinterpret_cast<const float4*>(
            &Wv[(size_t)(bk + 8 * i) * F_OUT + bq * 4]);
        pb[i] = make_float4(tf32f(v.x), tf32f(v.y), tf32f(v.z), tf32f(v.w));
    }

    float d[2][8][4];
#pragma unroll
    for (int mt = 0; mt < 2; ++mt)
#pragma unroll
        for (int nt = 0; nt < 8; ++nt)
#pragma unroll
            for (int c = 0; c < 4; ++c) d[mt][nt][c] = 0.f;

    for (int kt = 0; kt < F_IN / 32; ++kt) {
        // stage prefetched tile into smem
#pragma unroll
        for (int i = 0; i < 8; ++i)
            *reinterpret_cast<float4*>(&As[(ar + 16 * i) * A_STRIDE + aq * 4]) = pa[i];
#pragma unroll
        for (int i = 0; i < 4; ++i)
            *reinterpret_cast<float4*>(&Bs[(bk + 8 * i) * B_STRIDE + bq * 4]) = pb[i];
        __syncthreads();

        // prefetch next tile (overlaps with mma below)
        if (kt + 1 < F_IN / 32) {
            int k0n = (kt + 1) * 32;
#pragma unroll
            for (int i = 0; i < 8; ++i) {
                int gm = m0 + ar + 16 * i;
                pa[i] = (gm < n)
                    ? *reinterpret_cast<const float4*>(
                          &nf[(size_t)gm * F_IN + k0n + aq * 4])
                    : make_float4(0.f, 0.f, 0.f, 0.f);
            }
#pragma unroll
            for (int i = 0; i < 4; ++i) {
                float4 v = *reinterpret_cast<const float4*>(
                    &Wv[(size_t)(k0n + bk + 8 * i) * F_OUT + bq * 4]);
                pb[i] = make_float4(tf32f(v.x), tf32f(v.y), tf32f(v.z), tf32f(v.w));
            }
        }

        // mma over the smem tile
        const int fr = lane >> 2;   // fragment row 0..7
        const int fc = lane & 3;    // fragment col 0..3
        for (int kk = 0; kk < 32; kk += 8) {
            unsigned ahi[2][4], alo[2][4];
#pragma unroll
            for (int mt = 0; mt < 2; ++mt) {
                int r = w * 32 + mt * 16 + fr;
                float a0 = As[r * A_STRIDE + kk + fc];
                float a1 = As[(r + 8) * A_STRIDE + kk + fc];
                float a2 = As[r * A_STRIDE + kk + fc + 4];
                float a3 = As[(r + 8) * A_STRIDE + kk + fc + 4];
                ahi[mt][0] = tf32u(a0);
                ahi[mt][1] = tf32u(a1);
                ahi[mt][2] = tf32u(a2);
                ahi[mt][3] = tf32u(a3);
                alo[mt][0] = tf32u(a0 - __uint_as_float(ahi[mt][0]));
                alo[mt][1] = tf32u(a1 - __uint_as_float(ahi[mt][1]));
                alo[mt][2] = tf32u(a2 - __uint_as_float(ahi[mt][2]));
                alo[mt][3] = tf32u(a3 - __uint_as_float(ahi[mt][3]));
            }
#pragma unroll
            for (int nt = 0; nt < 8; ++nt) {
                unsigned b0 = __float_as_uint(
                    Bs[(kk + fc) * B_STRIDE + nt * 8 + fr]);
                unsigned b1 = __float_as_uint(
                    Bs[(kk + 4 + fc) * B_STRIDE + nt * 8 + fr]);
#pragma unroll
                for (int mt = 0; mt < 2; ++mt) {
                    mma_tf32(d[mt][nt], ahi[mt][0], ahi[mt][1], ahi[mt][2],
                             ahi[mt][3], b0, b1);
                    mma_tf32(d[mt][nt], alo[mt][0], alo[mt][1], alo[mt][2],
                             alo[mt][3], b0, b1);
                }
            }
        }
        __syncthreads();
    }

    // epilogue: write x and fused q/k
    const int fr = lane >> 2;
    const int fc = lane & 3;
#pragma unroll
    for (int mt = 0; mt < 2; ++mt) {
#pragma unroll
        for (int nt = 0; nt < 8; ++nt) {
            int col = nt * 8 + 2 * fc;
            int r0 = m0 + w * 32 + mt * 16 + fr;
            int r1 = r0 + 8;
            if (r0 < n)
                *reinterpret_cast<float2*>(&xout[(size_t)r0 * F_OUT + col]) =
                    make_float2(d[mt][nt][0], d[mt][nt][1]);
            if (r1 < n)
                *reinterpret_cast<float2*>(&xout[(size_t)r1 * F_OUT + col]) =
                    make_float2(d[mt][nt][2], d[mt][nt][3]);
        }
        // q/k for the two row-halves of this m-tile
#pragma unroll
        for (int half = 0; half < 2; ++half) {
            float qp = 0.f, kp = 0.f;
#pragma unroll
            for (int nt = 0; nt < 8; ++nt) {
                int col = nt * 8 + 2 * fc;
                float v0 = d[mt][nt][half * 2 + 0];
                float v1 = d[mt][nt][half * 2 + 1];
                qp += v0 * sWq[col] + v1 * sWq[col + 1];
                kp += v0 * sWk[col] + v1 * sWk[col + 1];
            }
            qp += __shfl_xor_sync(0xFFFFFFFFu, qp, 1);
            qp += __shfl_xor_sync(0xFFFFFFFFu, qp, 2);
            kp += __shfl_xor_sync(0xFFFFFFFFu, kp, 1);
            kp += __shfl_xor_sync(0xFFFFFFFFu, kp, 2);
            int r = m0 + w * 32 + mt * 16 + half * 8 + fr;
            if (fc == 0 && r < n) { qo[r] = qp; ko[r] = kp; }
        }
    }
}

// ---------------------------------------------------------------------------
// Kernel 2: row_ptr by binary search (row is sorted)
// ---------------------------------------------------------------------------
__global__ void rowptr_kernel(const int* __restrict__ row, int* __restrict__ rp,
                              int n, int e)
{
    int i = blockIdx.x * blockDim.x + threadIdx.x;
    if (i > n) return;
    int lo = 0, hi = e;
    while (lo < hi) {
        int mid = (lo + hi) >> 1;
        if (row[mid] < i) lo = mid + 1; else hi = mid;
    }
    rp[i] = lo;
}

// ---------------------------------------------------------------------------
// Kernel 3: fused segment softmax + aggregation (warp per node, single pass)
// (unchanged from R2 — known-good)
// ---------------------------------------------------------------------------
__global__ __launch_bounds__(256) void gat_kernel(
    const int* __restrict__ rp, const int* __restrict__ col,
    const float* __restrict__ x, const float* __restrict__ q,
    const float* __restrict__ kk, const float* __restrict__ b,
    float* __restrict__ out, int n)
{
    int i    = (blockIdx.x * blockDim.x + threadIdx.x) >> 5;
    int lane = threadIdx.x & 31;
    if (i >= n) return;

    const int half = lane >> 4;   // 0 or 1: which edge of the pair
    const int fl   = lane & 15;   // feature float4 index 0..15

    float4 bias = reinterpret_cast<const float4*>(b)[fl];
    float4* orow4 = reinterpret_cast<float4*>(&out[(size_t)i * F_OUT]);

    int s = rp[i], e = rp[i + 1];
    if (e == s) {               // empty segment: out = b
        if (half == 0) orow4[fl] = bias;
        return;
    }
    float qi = q[i];

    float4 acc = make_float4(0.f, 0.f, 0.f, 0.f);
    float ssum = 0.f;

    for (int base = s; base < e; base += 32) {
        int t = base + lane;
        float ev = 0.f;
        int c = 0;
        if (t < e) {
            c = col[t];
            float l = kk[c] + qi;
            l = (l > 0.f) ? l : 0.2f * l;
            ev = __expf(l);
        }
        ssum += ev;

        int cnt = min(e - base, 32);
        for (int j0 = 0; j0 < cnt; j0 += 2) {
            int j    = j0 + half;          // this half's edge slot
            int jsafe = min(j, cnt - 1);   // uniform, valid shfl source
            float w = __shfl_sync(0xFFFFFFFFu, ev, jsafe);
            int  cc = __shfl_sync(0xFFFFFFFFu, c,  jsafe);
            if (j < cnt) {
                float4 xv = reinterpret_cast<const float4*>(
                                &x[(size_t)cc * F_OUT])[fl];
                acc.x = fmaf(w, xv.x, acc.x);
                acc.y = fmaf(w, xv.y, acc.y);
                acc.z = fmaf(w, xv.z, acc.z);
                acc.w = fmaf(w, xv.w, acc.w);
            }
        }
    }

    // reduce denom across warp
#pragma unroll
    for (int o = 16; o; o >>= 1) ssum += __shfl_xor_sync(0xFFFFFFFFu, ssum, o);
    float inv = 1.0f / ssum;

    // combine the two half-warp accumulators (same features, different edges)
    acc.x += __shfl_xor_sync(0xFFFFFFFFu, acc.x, 16);
    acc.y += __shfl_xor_sync(0xFFFFFFFFu, acc.y, 16);
    acc.z += __shfl_xor_sync(0xFFFFFFFFu, acc.z, 16);
    acc.w += __shfl_xor_sync(0xFFFFFFFFu, acc.w, 16);

    if (half == 0) {
        float4 r;
        r.x = fmaf(acc.x, inv, bias.x);
        r.y = fmaf(acc.y, inv, bias.y);
        r.z = fmaf(acc.z, inv, bias.z);
        r.w = fmaf(acc.w, inv, bias.w);
        orow4[fl] = r;
    }
}

// ---------------------------------------------------------------------------
extern "C" void kernel_launch(void* const* d_in, const int* in_sizes, int n_in,
                              void* d_out, int out_size)
{
    const float* nf  = (const float*)d_in[0];   // [N, 256]
    const int*   row = (const int*)d_in[1];     // [E]
    const int*   col = (const int*)d_in[2];     // [E]
    const float* Wv  = (const float*)d_in[3];   // [256, 64]
    const float* wq  = (const float*)d_in[4];   // [64]
    const float* wk  = (const float*)d_in[5];   // [64]
    const float* b   = (const float*)d_in[6];   // [64]
    float* out = (float*)d_out;                  // [N, 64]

    const int n = NN;
    const int e = EE;

    float *xbuf, *qbuf, *kbuf;
    int *rpbuf;
    cudaGetSymbolAddress((void**)&xbuf, g_x);
    cudaGetSymbolAddress((void**)&qbuf, g_q);
    cudaGetSymbolAddress((void**)&kbuf, g_k);
    cudaGetSymbolAddress((void**)&rpbuf, g_rp);

    // 1) projection GEMM (tensor cores) + fused q/k epilogue
    gemm_tc_kernel<<<(n + 127) / 128, 128>>>(nf, Wv, wq, wk, xbuf, qbuf, kbuf, n);
    // 2) CSR offsets
    rowptr_kernel<<<(n + 1 + 255) / 256, 256>>>(row, rpbuf, n, e);
    // 3) fused softmax + aggregation (warp per node)
    gat_kernel<<<(n + 7) / 8, 256>>>(rpbuf, col, xbuf, qbuf, kbuf, b, out, n);
}

// round 5
// speedup vs baseline: 1.7949x; 1.1005x over previous
#include <cuda_runtime.h>
#include <cuda_bf16.h>
#include <cuda_fp16.h>
#include <math.h>

// Problem constants (match reference)
#define NN 100000
#define EE 1600000
#define F_IN 256
#define F_OUT 64

// Scratch (device globals; no runtime allocation allowed)
__device__ __half g_xh[(size_t)NN * F_OUT];  // projected features (fp16)
__device__ float  g_q[NN];
__device__ float  g_k[NN];
__device__ int    g_rp[NN + 1];

// ---------------------------------------------------------------------------
// tf32 helpers
// ---------------------------------------------------------------------------
__device__ __forceinline__ unsigned tf32u(float x) {
    unsigned u;
    asm("cvt.rna.tf32.f32 %0, %1;" : "=r"(u) : "f"(x));
    return u;
}
__device__ __forceinline__ void mma_tf32(float* d,
    unsigned a0, unsigned a1, unsigned a2, unsigned a3,
    unsigned b0, unsigned b1)
{
    asm("mma.sync.aligned.m16n8k8.row.col.f32.tf32.tf32.f32 "
        "{%0,%1,%2,%3},{%4,%5,%6,%7},{%8,%9},{%0,%1,%2,%3};"
        : "+f"(d[0]), "+f"(d[1]), "+f"(d[2]), "+f"(d[3])
        : "r"(a0), "r"(a1), "r"(a2), "r"(a3), "r"(b0), "r"(b1));
}

// ---------------------------------------------------------------------------
// Kernel 1: x = nf @ Wv via tf32 tensor cores, single pass (A and B both
// rna-rounded at staging; smem holds tf32 -> inner loop is pure LDS+MMA).
// BM=128, BK=32, 128 threads = 4 warps; warp w owns rows [32w, 32w+32).
// Epilogue: x written as fp16; q/k fused via shfl reduction.
// ---------------------------------------------------------------------------
#define A_STRIDE 36   // words per A row in smem (conflict-free frag loads)
#define B_STRIDE 72   // words per B row in smem

__global__ __launch_bounds__(128) void gemm_tc_kernel(
    const float* __restrict__ nf, const float* __restrict__ Wv,
    const float* __restrict__ wq, const float* __restrict__ wk,
    __half* __restrict__ xh, float* __restrict__ qo, float* __restrict__ ko,
    int n)
{
    __shared__ __align__(16) unsigned As[128 * A_STRIDE];  // tf32 A 128x32
    __shared__ __align__(16) unsigned Bs[32 * B_STRIDE];   // tf32 B 32x64
    __shared__ float sWq[64], sWk[64];

    const int t    = threadIdx.x;
    const int lane = t & 31;
    const int w    = t >> 5;
    const int m0   = blockIdx.x * 128;

    if (t < 64) { sWq[t] = wq[t]; sWk[t] = wk[t]; }

    // load mappings
    const int aq = t & 7;          // A col-quad 0..7
    const int ar = t >> 3;         // A base row 0..15 (+16*i)
    const int bq = t & 15;         // B col-quad 0..15
    const int bk = t >> 4;         // B base k 0..7 (+8*i)

    float4 pa[8];
    float4 pb[4];

    // prefetch tile 0
#pragma unroll
    for (int i = 0; i < 8; ++i) {
        int gm = m0 + ar + 16 * i;
        pa[i] = (gm < n)
            ? *reinterpret_cast<const float4*>(&nf[(size_t)gm * F_IN + aq * 4])
            : make_float4(0.f, 0.f, 0.f, 0.f);
    }
#pragma unroll
    for (int i = 0; i < 4; ++i)
        pb[i] = *reinterpret_cast<const float4*>(
            &Wv[(size_t)(bk + 8 * i) * F_OUT + bq * 4]);

    float d[2][8][4];
#pragma unroll
    for (int mt = 0; mt < 2; ++mt)
#pragma unroll
        for (int nt = 0; nt < 8; ++nt)
#pragma unroll
            for (int c = 0; c < 4; ++c) d[mt][nt][c] = 0.f;

    const int fr = lane >> 2;   // fragment row 0..7
    const int fc = lane & 3;    // fragment col 0..3

    for (int kt = 0; kt < F_IN / 32; ++kt) {
        // stage prefetched tile into smem, converting to tf32
#pragma unroll
        for (int i = 0; i < 8; ++i) {
            uint4 u = make_uint4(tf32u(pa[i].x), tf32u(pa[i].y),
                                 tf32u(pa[i].z), tf32u(pa[i].w));
            *reinterpret_cast<uint4*>(&As[(ar + 16 * i) * A_STRIDE + aq * 4]) = u;
        }
#pragma unroll
        for (int i = 0; i < 4; ++i) {
            uint4 u = make_uint4(tf32u(pb[i].x), tf32u(pb[i].y),
                                 tf32u(pb[i].z), tf32u(pb[i].w));
            *reinterpret_cast<uint4*>(&Bs[(bk + 8 * i) * B_STRIDE + bq * 4]) = u;
        }
        __syncthreads();

        // prefetch next tile (overlaps with mma below)
        if (kt + 1 < F_IN / 32) {
            int k0n = (kt + 1) * 32;
#pragma unroll
            for (int i = 0; i < 8; ++i) {
                int gm = m0 + ar + 16 * i;
                pa[i] = (gm < n)
                    ? *reinterpret_cast<const float4*>(
                          &nf[(size_t)gm * F_IN + k0n + aq * 4])
                    : make_float4(0.f, 0.f, 0.f, 0.f);
            }
#pragma unroll
            for (int i = 0; i < 4; ++i)
                pb[i] = *reinterpret_cast<const float4*>(
                    &Wv[(size_t)(k0n + bk + 8 * i) * F_OUT + bq * 4]);
        }

        // mma over the smem tile: pure LDS + MMA
#pragma unroll
        for (int kk = 0; kk < 32; kk += 8) {
            unsigned a[2][4];
#pragma unroll
            for (int mt = 0; mt < 2; ++mt) {
                int r = w * 32 + mt * 16 + fr;
                a[mt][0] = As[r * A_STRIDE + kk + fc];
                a[mt][1] = As[(r + 8) * A_STRIDE + kk + fc];
                a[mt][2] = As[r * A_STRIDE + kk + fc + 4];
                a[mt][3] = As[(r + 8) * A_STRIDE + kk + fc + 4];
            }
#pragma unroll
            for (int nt = 0; nt < 8; ++nt) {
                unsigned b0 = Bs[(kk + fc) * B_STRIDE + nt * 8 + fr];
                unsigned b1 = Bs[(kk + 4 + fc) * B_STRIDE + nt * 8 + fr];
                mma_tf32(d[0][nt], a[0][0], a[0][1], a[0][2], a[0][3], b0, b1);
                mma_tf32(d[1][nt], a[1][0], a[1][1], a[1][2], a[1][3], b0, b1);
            }
        }
        __syncthreads();
    }

    // epilogue: write x (fp16) and fused q/k
#pragma unroll
    for (int mt = 0; mt < 2; ++mt) {
#pragma unroll
        for (int nt = 0; nt < 8; ++nt) {
            int col = nt * 8 + 2 * fc;
            int r0 = m0 + w * 32 + mt * 16 + fr;
            int r1 = r0 + 8;
            if (r0 < n)
                *reinterpret_cast<half2*>(&xh[(size_t)r0 * F_OUT + col]) =
                    __floats2half2_rn(d[mt][nt][0], d[mt][nt][1]);
            if (r1 < n)
                *reinterpret_cast<half2*>(&xh[(size_t)r1 * F_OUT + col]) =
                    __floats2half2_rn(d[mt][nt][2], d[mt][nt][3]);
        }
        // q/k for the two row-halves of this m-tile
#pragma unroll
        for (int half = 0; half < 2; ++half) {
            float qp = 0.f, kp = 0.f;
#pragma unroll
            for (int nt = 0; nt < 8; ++nt) {
                int col = nt * 8 + 2 * fc;
                float v0 = d[mt][nt][half * 2 + 0];
                float v1 = d[mt][nt][half * 2 + 1];
                qp += v0 * sWq[col] + v1 * sWq[col + 1];
                kp += v0 * sWk[col] + v1 * sWk[col + 1];
            }
            qp += __shfl_xor_sync(0xFFFFFFFFu, qp, 1);
            qp += __shfl_xor_sync(0xFFFFFFFFu, qp, 2);
            kp += __shfl_xor_sync(0xFFFFFFFFu, kp, 1);
            kp += __shfl_xor_sync(0xFFFFFFFFu, kp, 2);
            int r = m0 + w * 32 + mt * 16 + half * 8 + fr;
            if (fc == 0 && r < n) { qo[r] = qp; ko[r] = kp; }
        }
    }
}

// ---------------------------------------------------------------------------
// Kernel 2: row_ptr by binary search (row is sorted)
// ---------------------------------------------------------------------------
__global__ void rowptr_kernel(const int* __restrict__ row, int* __restrict__ rp,
                              int n, int e)
{
    int i = blockIdx.x * blockDim.x + threadIdx.x;
    if (i > n) return;
    int lo = 0, hi = e;
    while (lo < hi) {
        int mid = (lo + hi) >> 1;
        if (row[mid] < i) lo = mid + 1; else hi = mid;
    }
    rp[i] = lo;
}

// ---------------------------------------------------------------------------
// Kernel 3: fused segment softmax + aggregation (warp per node, single pass)
// x gathered in fp16 (128B/row): 4 edges/step, 8 lanes x 16B (LDG.128) each,
// fp32 accumulation. Shfl trip counts are warp-uniform (clamped slot index);
// only the gather/FMA is predicated.
// ---------------------------------------------------------------------------
__global__ __launch_bounds__(256) void gat_kernel(
    const int* __restrict__ rp, const int* __restrict__ col,
    const __half* __restrict__ xh, const float* __restrict__ q,
    const float* __restrict__ kk, const float* __restrict__ b,
    float* __restrict__ out, int n)
{
    int i    = (blockIdx.x * blockDim.x + threadIdx.x) >> 5;
    int lane = threadIdx.x & 31;
    if (i >= n) return;

    const int eighth = lane >> 3;  // 0..3: which edge of the quad
    const int fl     = lane & 7;   // 16B chunk 0..7 -> features fl*8..fl*8+7

    // bias chunk for this lane's 8 features
    float4 b0 = reinterpret_cast<const float4*>(b)[fl * 2];
    float4 b1 = reinterpret_cast<const float4*>(b)[fl * 2 + 1];
    float* orow = &out[(size_t)i * F_OUT];

    int s = rp[i], e = rp[i + 1];
    if (e == s) {               // empty segment: out = b
        if (eighth == 0) {
            *reinterpret_cast<float4*>(&orow[fl * 8])     = b0;
            *reinterpret_cast<float4*>(&orow[fl * 8 + 4]) = b1;
        }
        return;
    }
    float qi = q[i];

    float acc[8];
#pragma unroll
    for (int z = 0; z < 8; ++z) acc[z] = 0.f;
    float ssum = 0.f;

    for (int base = s; base < e; base += 32) {
        int t = base + lane;
        float ev = 0.f;
        int c = 0;
        if (t < e) {
            c = col[t];
            float l = kk[c] + qi;
            l = (l > 0.f) ? l : 0.2f * l;
            ev = __expf(l);
        }
        ssum += ev;

        int cnt = min(e - base, 32);
        for (int j0 = 0; j0 < cnt; j0 += 4) {
            int j     = j0 + eighth;        // this quad-slot's edge
            int jsafe = min(j, cnt - 1);    // uniform, valid shfl source
            float w = __shfl_sync(0xFFFFFFFFu, ev, jsafe);
            int  cc = __shfl_sync(0xFFFFFFFFu, c,  jsafe);
            if (j < cnt) {
                const uint4 hv = *reinterpret_cast<const uint4*>(
                    &xh[(size_t)cc * F_OUT + fl * 8]);
                float2 f0 = __half22float2(*reinterpret_cast<const half2*>(&hv.x));
                float2 f1 = __half22float2(*reinterpret_cast<const half2*>(&hv.y));
                float2 f2 = __half22float2(*reinterpret_cast<const half2*>(&hv.z));
                float2 f3 = __half22float2(*reinterpret_cast<const half2*>(&hv.w));
                acc[0] = fmaf(w, f0.x, acc[0]);
                acc[1] = fmaf(w, f0.y, acc[1]);
                acc[2] = fmaf(w, f1.x, acc[2]);
                acc[3] = fmaf(w, f1.y, acc[3]);
                acc[4] = fmaf(w, f2.x, acc[4]);
                acc[5] = fmaf(w, f2.y, acc[5]);
                acc[6] = fmaf(w, f3.x, acc[6]);
                acc[7] = fmaf(w, f3.y, acc[7]);
            }
        }
    }

    // reduce denom across warp
#pragma unroll
    for (int o = 16; o; o >>= 1) ssum += __shfl_xor_sync(0xFFFFFFFFu, ssum, o);
    float inv = 1.0f / ssum;

    // combine the four quad accumulators (same features, different edges)
#pragma unroll
    for (int z = 0; z < 8; ++z) {
        acc[z] += __shfl_xor_sync(0xFFFFFFFFu, acc[z], 8);
        acc[z] += __shfl_xor_sync(0xFFFFFFFFu, acc[z], 16);
    }

    if (eighth == 0) {
        float4 r0, r1;
        r0.x = fmaf(acc[0], inv, b0.x);
        r0.y = fmaf(acc[1], inv, b0.y);
        r0.z = fmaf(acc[2], inv, b0.z);
        r0.w = fmaf(acc[3], inv, b0.w);
        r1.x = fmaf(acc[4], inv, b1.x);
        r1.y = fmaf(acc[5], inv, b1.y);
        r1.z = fmaf(acc[6], inv, b1.z);
        r1.w = fmaf(acc[7], inv, b1.w);
        *reinterpret_cast<float4*>(&orow[fl * 8])     = r0;
        *reinterpret_cast<float4*>(&orow[fl * 8 + 4]) = r1;
    }
}

// ---------------------------------------------------------------------------
extern "C" void kernel_launch(void* const* d_in, const int* in_sizes, int n_in,
                              void* d_out, int out_size)
{
    const float* nf  = (const float*)d_in[0];   // [N, 256]
    const int*   row = (const int*)d_in[1];     // [E]
    const int*   col = (const int*)d_in[2];     // [E]
    const float* Wv  = (const float*)d_in[3];   // [256, 64]
    const float* wq  = (const float*)d_in[4];   // [64]
    const float* wk  = (const float*)d_in[5];   // [64]
    const float* b   = (const float*)d_in[6];   // [64]
    float* out = (float*)d_out;                  // [N, 64]

    const int n = NN;
    const int e = EE;

    __half* xhbuf;
    float *qbuf, *kbuf;
    int *rpbuf;
    cudaGetSymbolAddress((void**)&xhbuf, g_xh);
    cudaGetSymbolAddress((void**)&qbuf, g_q);
    cudaGetSymbolAddress((void**)&kbuf, g_k);
    cudaGetSymbolAddress((void**)&rpbuf, g_rp);

    // 1) projection GEMM (tf32 single pass) + fused q/k epilogue, fp16 x out
    gemm_tc_kernel<<<(n + 127) / 128, 128>>>(nf, Wv, wq, wk, xhbuf, qbuf, kbuf, n);
    // 2) CSR offsets
    rowptr_kernel<<<(n + 1 + 255) / 256, 256>>>(row, rpbuf, n, e);
    // 3) fused softmax + aggregation (warp per node)
    gat_kernel<<<(n + 7) / 8, 256>>>(rpbuf, col, xhbuf, qbuf, kbuf, b, out, n);
}